// round 7
// baseline (speedup 1.0000x reference)
#include <cuda_runtime.h>

#define EPS 1e-7f
#define NDIM 64
#define TBINS 64
#define NKEY (NDIM * TBINS)          // 4096 sort keys
#define MAXN 32768
#define MAXR 2048
#define MAXCHUNKS 128
#define TPB 128   // Ks kernel threads per block
#define RPT 4     // r values per thread in Ks kernel
#define NSPLIT 4  // point-splits for Ks
#define NSPLITC 2 // point-splits for Kc
#define DW 0.19f  // Kc window half-width: exp(-500*0.19^2)=1.5e-8
#define LOG2E 1.4426950408889634f
#define VSCALE 8388608.0f
#define VSCALE_INV 1.1920928955078125e-7f

typedef unsigned long long ull;

// ---------------- device scratch ----------------
__device__ ulonglong2 g_bc[MAXN];               // {B,B},{C,C} per point, (d,tbin)-sorted
__device__ ull    g_vv[MAXN];                   // {v,v}
__device__ int    g_binoff[NKEY + 1];           // global offset per key
__device__ int    g_chunkhistT[NKEY][MAXCHUNKS];
__device__ int    g_chunkcumT [NKEY][MAXCHUNKS];
__device__ ull    g_chunkvsum[MAXCHUNKS][NDIM];
__device__ float  g_sumv[NDIM];
__device__ float  g_Sws [NSPLIT ][NDIM * MAXR]; // sum e
__device__ float  g_Swsv[NSPLIT ][NDIM * MAXR]; // sum e*v
__device__ float  g_Swc [NSPLITC][NDIM * MAXR]; // sum e^10
__device__ float  g_Swcv[NSPLITC][NDIM * MAXR]; // sum e^10*v

// ---------------- f32x2 packed helpers (sm_100a) ----------------
__device__ __forceinline__ ull pack2(float lo, float hi) {
    ull r; asm("mov.b64 %0, {%1, %2};" : "=l"(r) : "f"(lo), "f"(hi)); return r;
}
__device__ __forceinline__ void unpack2(ull p, float& lo, float& hi) {
    asm("mov.b64 {%0, %1}, %2;" : "=f"(lo), "=f"(hi) : "l"(p));
}
__device__ __forceinline__ ull add2(ull a, ull b) {
    ull r; asm("add.rn.f32x2 %0, %1, %2;" : "=l"(r) : "l"(a), "l"(b)); return r;
}
__device__ __forceinline__ ull fma2(ull a, ull b, ull c) {
    ull r; asm("fma.rn.f32x2 %0, %1, %2, %3;" : "=l"(r) : "l"(a), "l"(b), "l"(c)); return r;
}
__device__ __forceinline__ float ex2f(float x) {
    float y; asm("ex2.approx.f32 %0, %1;" : "=f"(y) : "f"(x)); return y;
}

// ---------------- P1: per-chunk 4096-key histogram + per-dim v sums ----------------
__global__ void k_hist(const float* __restrict__ S, int n) {
    __shared__ int h[NKEY];
    __shared__ ull vs[NDIM];
    const int tid = threadIdx.x;
    for (int j = tid; j < NKEY; j += 256) h[j] = 0;
    if (tid < NDIM) vs[tid] = 0ULL;
    __syncthreads();
    int i = blockIdx.x * 256 + tid;
    if (i < n) {
        float t = S[i * 3 + 0];
        float v = S[i * 3 + 1];
        int d = (int)S[i * 3 + 2];
        int tb = (int)(t * (float)TBINS);
        tb = max(0, min(TBINS - 1, tb));
        atomicAdd(&h[d * TBINS + tb], 1);
        atomicAdd(&vs[d], (ull)(long long)llrintf(v * VSCALE));
    }
    __syncthreads();
    for (int j = tid; j < NKEY; j += 256) g_chunkhistT[j][blockIdx.x] = h[j];
    if (tid < NDIM) g_chunkvsum[blockIdx.x][tid] = vs[tid];
}

// ---------------- P2: scan (1 block, 256 threads; each owns 16 keys) ----------------
__global__ void k_scan(int nchunks) {
    const int tid = threadIdx.x;
    int tot[16], lpre[16];
#pragma unroll
    for (int q = 0; q < 16; q++) {
        const int key = tid * 16 + q;
        int run = 0;
        for (int c = 0; c < nchunks; c++) {
            int x = g_chunkhistT[key][c];
            g_chunkcumT[key][c] = run;
            run += x;
        }
        tot[q] = run;
    }
    int lsum = 0;
#pragma unroll
    for (int q = 0; q < 16; q++) { lpre[q] = lsum; lsum += tot[q]; }
    __shared__ int ssum[256];
    ssum[tid] = lsum;
    __syncthreads();
    for (int ofs = 1; ofs < 256; ofs <<= 1) {        // Hillis-Steele inclusive scan
        int v = (tid >= ofs) ? ssum[tid - ofs] : 0;
        __syncthreads();
        ssum[tid] += v;
        __syncthreads();
    }
    const int base = ssum[tid] - lsum;               // exclusive prefix
#pragma unroll
    for (int q = 0; q < 16; q++) g_binoff[tid * 16 + q] = base + lpre[q];
    if (tid == 255) g_binoff[NKEY] = base + lsum;
}

// ---------------- P3: stable scatter + point preprocessing ----------------
__global__ void k_scatter(const float* __restrict__ S,
                          const float* __restrict__ alpha,
                          int n, int nchunks) {
    __shared__ int   keys[256];
    __shared__ float st[256], sv[256];
    const int tid = threadIdx.x;
    const int c   = blockIdx.x;

    if (c == 0 && tid < NDIM) {          // publish per-dim v sums
        ull acc = 0ULL;
        for (int cc = 0; cc < nchunks; cc++) acc += g_chunkvsum[cc][tid];
        g_sumv[tid] = (float)((long long)acc) * VSCALE_INV;
    }

    int i = c * 256 + tid;
    int key = -1;
    if (i < n) {
        float t = S[i * 3 + 0];
        st[tid] = t;
        sv[tid] = S[i * 3 + 1];
        int d = (int)S[i * 3 + 2];
        int tb = (int)(t * (float)TBINS);
        tb = max(0, min(TBINS - 1, tb));
        key = d * TBINS + tb;
    }
    keys[tid] = key;
    __syncthreads();
    if (key >= 0) {
        int rank = 0;
        for (int j = 0; j < tid; j++) rank += (keys[j] == key);
        int pos = g_binoff[key] + g_chunkcumT[key][c] + rank;

        float t = st[tid];
        float tm = (t > 0.0f) ? t : 1.0e9f;     // masked -> exp underflows to 0
        float negC = -__ldg(alpha) * LOG2E;
        float B = -2.0f * negC * tm;            // arg = A + B*r + C = negC*(r-t)^2
        float Cc = negC * tm * tm;
        ulonglong2 bc;
        bc.x = pack2(B, B);
        bc.y = pack2(Cc, Cc);
        g_bc[pos] = bc;
        g_vv[pos] = pack2(sv[tid], sv[tid]);
    }
}

// ---------------- Ks kernel: full 67M pairs, light body ----------------
// grid = (R/(TPB*RPT)=4, NDIM, NSPLIT=4) = 1024 CTAs x 128 thr
__global__ void __launch_bounds__(TPB) k_main_s(const float* __restrict__ ref,
                                                const float* __restrict__ alpha,
                                                int R) {
    const int d   = blockIdx.y;
    const int z   = blockIdx.z;
    const int lo0 = g_binoff[d * TBINS];
    const int len = g_binoff[(d + 1) * TBINS] - lo0;
    const int lo  = lo0 + (len * z) / NSPLIT;
    const int hi  = lo0 + (len * (z + 1)) / NSPLIT;
    const int tid = threadIdx.x;
    const int r0  = blockIdx.x * (TPB * RPT) + tid;

    const float negC = -__ldg(alpha) * LOG2E;
    const float f0 = __ldg(ref + r0),           f1 = __ldg(ref + r0 + TPB);
    const float f2 = __ldg(ref + r0 + 2 * TPB), f3 = __ldg(ref + r0 + 3 * TPB);
    const ull rr01 = pack2(f0, f1);
    const ull rr23 = pack2(f2, f3);
    const ull A01  = pack2(negC * f0 * f0, negC * f1 * f1);
    const ull A23  = pack2(negC * f2 * f2, negC * f3 * f3);

    ull ws01 = 0, wsv01 = 0, ws23 = 0, wsv23 = 0;

#pragma unroll 4
    for (int i = lo; i < hi; i++) {
        ulonglong2 bc = __ldg(&g_bc[i]);
        ull vp = __ldg(&g_vv[i]);

        ull pc01 = add2(bc.y, A01);
        ull pc23 = add2(bc.y, A23);
        ull g01  = fma2(bc.x, rr01, pc01);    // negC*(r-t)^2 in log2 domain
        ull g23  = fma2(bc.x, rr23, pc23);

        float a0, a1, a2, a3;
        unpack2(g01, a0, a1);
        unpack2(g23, a2, a3);
        ull e01 = pack2(ex2f(a0), ex2f(a1));
        ull e23 = pack2(ex2f(a2), ex2f(a3));

        ws01  = add2(ws01, e01);
        wsv01 = fma2(e01, vp, wsv01);
        ws23  = add2(ws23, e23);
        wsv23 = fma2(e23, vp, wsv23);
    }

    float x0, x1;
    const int base = d * R + r0;
    unpack2(ws01,  x0, x1); g_Sws [z][base] = x0; g_Sws [z][base + TPB] = x1;
    unpack2(ws23,  x0, x1); g_Sws [z][base + 2 * TPB] = x0; g_Sws [z][base + 3 * TPB] = x1;
    unpack2(wsv01, x0, x1); g_Swsv[z][base] = x0; g_Swsv[z][base + TPB] = x1;
    unpack2(wsv23, x0, x1); g_Swsv[z][base + 2 * TPB] = x0; g_Swsv[z][base + 3 * TPB] = x1;
}

// ---------------- Kc kernel: windowed pairs, e^10 = ex2(10*arg) ----------------
// grid = (R/128=16, NDIM, NSPLITC=2), 64 threads; block covers 128 contiguous r's
__global__ void __launch_bounds__(64) k_main_c(const float* __restrict__ ref,
                                               const float* __restrict__ alpha,
                                               int R) {
    const int d   = blockIdx.y;
    const int z   = blockIdx.z;
    const int tid = threadIdx.x;
    const int rb  = blockIdx.x * 128;

    const float negC10 = -10.0f * __ldg(alpha) * LOG2E;
    const float f0 = __ldg(ref + rb + tid);
    const float f1 = __ldg(ref + rb + tid + 64);
    const ull rr01 = pack2(10.0f * f0,10.0f * f1);          // 10*r
    const ull A01  = pack2(negC10 * f0 * f0, negC10 * f1 * f1);
    const ull TEN2 = pack2(10.0f, 10.0f);

    // window: bins intersecting [rlo-DW, rhi+DW]
    const float rlo = __ldg(ref + rb);
    const float rhi = __ldg(ref + rb + 127);
    int b0 = (int)floorf((rlo - DW) * (float)TBINS);
    int b1 = (int)floorf((rhi + DW) * (float)TBINS) + 1;
    b0 = max(0, b0); b1 = min(TBINS, b1);
    const int p0  = g_binoff[d * TBINS + b0];
    const int p1  = g_binoff[d * TBINS + b1];
    const int len = p1 - p0;
    const int lo  = p0 + (len * z) / NSPLITC;
    const int hi  = p0 + (len * (z + 1)) / NSPLITC;

    ull wc01 = 0, wcv01 = 0;

#pragma unroll 4
    for (int i = lo; i < hi; i++) {
        ulonglong2 bc = __ldg(&g_bc[i]);      // {B,B},{C,C}
        ull vp = __ldg(&g_vv[i]);

        ull pc  = fma2(bc.y, TEN2, A01);      // 10C + 10A
        ull g01 = fma2(bc.x, rr01, pc);       // B*(10r) + 10C + 10A = 10*arg

        float a0, a1;
        unpack2(g01, a0, a1);
        ull e01 = pack2(ex2f(a0), ex2f(a1));  // e^10 directly

        wc01  = add2(wc01, e01);
        wcv01 = fma2(e01, vp, wcv01);
    }

    float x0, x1;
    const int base = d * R + rb + tid;
    unpack2(wc01,  x0, x1); g_Swc [z][base] = x0; g_Swc [z][base + 64] = x1;
    unpack2(wcv01, x0, x1); g_Swcv[z][base] = x0; g_Swcv[z][base + 64] = x1;
}

// ---------------- finalize: 512 blocks x 256 thr, 4 r's per block ----------------
__global__ void __launch_bounds__(256) k_finalize(const float* __restrict__ rho,
                                                  float* __restrict__ out,
                                                  int R, float Rinv) {
    __shared__ float s_lam[4][NDIM + 1];
    __shared__ float s_ksv[4][NDIM + 1];
    __shared__ float s_coa[4][NDIM + 1];
    __shared__ float s_den[4];

    const int tid = threadIdx.x;
    const int r0  = blockIdx.x * 4;

    {
        const int d   = tid >> 2;
        const int rl  = tid & 3;
        const int idx = d * R + r0 + rl;
        const int cnt = g_binoff[(d + 1) * TBINS] - g_binoff[d * TBINS];
        const float ec = EPS * (float)(cnt + 1);
        const float ev = EPS * g_sumv[d];
        float lam_s = g_Sws [0][idx] + g_Sws [1][idx] + g_Sws [2][idx] + g_Sws [3][idx] + ec;
        float ksv   = g_Swsv[0][idx] + g_Swsv[1][idx] + g_Swsv[2][idx] + g_Swsv[3][idx] + ev;
        float lam_c = g_Swc [0][idx] + g_Swc [1][idx] + ec;
        float kcv   = g_Swcv[0][idx] + g_Swcv[1][idx] + ev;
        s_lam[rl][d] = lam_s;
        s_ksv[rl][d] = ksv;
        s_coa[rl][d] = __fdividef(kcv, lam_c);
    }
    __syncthreads();

    {
        const int wid  = tid >> 5;
        const int lane = tid & 31;
        if (wid < 4) {
            float p = s_lam[wid][lane] + s_lam[wid][lane + 32];
            p += __shfl_xor_sync(0xffffffffu, p, 16);
            p += __shfl_xor_sync(0xffffffffu, p, 8);
            p += __shfl_xor_sync(0xffffffffu, p, 4);
            p += __shfl_xor_sync(0xffffffffu, p, 2);
            p += __shfl_xor_sync(0xffffffffu, p, 1);
            if (lane == 0) s_den[wid] = p;
        }
    }
    __syncthreads();

    const int d  = tid & 63;
    const int rl = tid >> 6;
    float acc = 0.0f;
#pragma unroll
    for (int k = 0; k < NDIM; k++)
        acc = fmaf(s_ksv[rl][k], __ldg(&rho[k * NDIM + d]), acc);
    const float cr = __fdividef(acc, s_den[rl]);

    const int r = r0 + rl;
    float* o = out + (long long)r * (3 * NDIM);
    o[d]            = s_lam[rl][d] * Rinv;   // lam
    o[NDIM + d]     = cr;                    // cross
    o[2 * NDIM + d] = s_coa[rl][d] - cr;     // transient
}

// ---------------- launch ----------------
extern "C" void kernel_launch(void* const* d_in, const int* in_sizes, int n_in,
                              void* d_out, int out_size) {
    const float* S     = (const float*)d_in[0];
    const float* ref   = (const float*)d_in[1];
    const float* alpha = (const float*)d_in[2];
    const float* rho   = (const float*)d_in[3];
    const int n = in_sizes[0] / 3;
    const int R = in_sizes[1];
    int nchunks = (n + 255) / 256;
    if (nchunks > MAXCHUNKS) nchunks = MAXCHUNKS;

    k_hist<<<nchunks, 256>>>(S, n);
    k_scan<<<1, 256>>>(nchunks);
    k_scatter<<<nchunks, 256>>>(S, alpha, n, nchunks);

    dim3 gs(R / (TPB * RPT), NDIM, NSPLIT);
    k_main_s<<<gs, TPB>>>(ref, alpha, R);

    dim3 gc(R / 128, NDIM, NSPLITC);
    k_main_c<<<gc, 64>>>(ref, alpha, R);

    k_finalize<<<R / 4, 256>>>(rho, (float*)d_out, R, 1.0f / (float)R);
}

// round 8
// speedup vs baseline: 7.6730x; 7.6730x over previous
#include <cuda_runtime.h>

#define EPS 1e-7f
#define NDIM 64
#define TBINS 64
#define NKEY (NDIM * TBINS)          // 4096 sort keys
#define MAXN 32768
#define MAXR 2048
#define MAXCHUNKS 128
#define TPB 128   // Ks kernel threads per block
#define RPT 4     // r values per thread in Ks kernel
#define NSPLIT 8  // point-splits for Ks
#define NSPLITC 2 // point-splits for Kc
#define DW 0.19f  // Kc window half-width: exp(-500*0.19^2)=1.5e-8
#define LOG2E 1.4426950408889634f
#define VSCALE 8388608.0f
#define VSCALE_INV 1.1920928955078125e-7f

typedef unsigned long long ull;

// ---------------- device scratch ----------------
__device__ ulonglong2 g_bc[MAXN];               // {B,B},{C,C} per point, (d,tbin)-sorted
__device__ ull    g_vv[MAXN];                   // {v,v}
__device__ int    g_binoff[NKEY + 1];           // global offset per key
__device__ int    g_keytot[NKEY];               // total count per key
__device__ int    g_chunkhist[MAXCHUNKS][NKEY]; // [chunk][key] (coalesced)
__device__ int    g_chunkcum [MAXCHUNKS][NKEY]; // exclusive chunk prefix per key
__device__ ull    g_chunkvsum[MAXCHUNKS][NDIM];
__device__ float  g_sumv[NDIM];
__device__ float  g_Sws [NSPLIT ][NDIM * MAXR]; // sum e
__device__ float  g_Swsv[NSPLIT ][NDIM * MAXR]; // sum e*v
__device__ float  g_Swc [NSPLITC][NDIM * MAXR]; // sum e^10
__device__ float  g_Swcv[NSPLITC][NDIM * MAXR]; // sum e^10*v

// ---------------- f32x2 packed helpers (sm_100a) ----------------
__device__ __forceinline__ ull pack2(float lo, float hi) {
    ull r; asm("mov.b64 %0, {%1, %2};" : "=l"(r) : "f"(lo), "f"(hi)); return r;
}
__device__ __forceinline__ void unpack2(ull p, float& lo, float& hi) {
    asm("mov.b64 {%0, %1}, %2;" : "=f"(lo), "=f"(hi) : "l"(p));
}
__device__ __forceinline__ ull add2(ull a, ull b) {
    ull r; asm("add.rn.f32x2 %0, %1, %2;" : "=l"(r) : "l"(a), "l"(b)); return r;
}
__device__ __forceinline__ ull fma2(ull a, ull b, ull c) {
    ull r; asm("fma.rn.f32x2 %0, %1, %2, %3;" : "=l"(r) : "l"(a), "l"(b), "l"(c)); return r;
}
__device__ __forceinline__ float ex2f(float x) {
    float y; asm("ex2.approx.f32 %0, %1;" : "=f"(y) : "f"(x)); return y;
}

// ---------------- P1: per-chunk 4096-key histogram + per-dim v sums ----------------
__global__ void k_hist(const float* __restrict__ S, int n) {
    __shared__ int h[NKEY];
    __shared__ ull vs[NDIM];
    const int tid = threadIdx.x;
    for (int j = tid; j < NKEY; j += 256) h[j] = 0;
    if (tid < NDIM) vs[tid] = 0ULL;
    __syncthreads();
    int i = blockIdx.x * 256 + tid;
    if (i < n) {
        float t = S[i * 3 + 0];
        float v = S[i * 3 + 1];
        int d = (int)S[i * 3 + 2];
        int tb = (int)(t * (float)TBINS);
        tb = max(0, min(TBINS - 1, tb));
        atomicAdd(&h[d * TBINS + tb], 1);
        atomicAdd(&vs[d], (ull)(long long)llrintf(v * VSCALE));
    }
    __syncthreads();
    for (int j = tid; j < NKEY; j += 256) g_chunkhist[blockIdx.x][j] = h[j];  // coalesced
    if (tid < NDIM) g_chunkvsum[blockIdx.x][tid] = vs[tid];
}

// ---------------- P2a: per-key chunk scan (16 blocks x 256 thr, 1 thread/key) ----------
__global__ void k_scan1(int nchunks) {
    const int key = blockIdx.x * 256 + threadIdx.x;   // 4096 threads
    int run = 0;
    for (int c = 0; c < nchunks; c++) {               // coalesced across threads
        int x = g_chunkhist[c][key];
        g_chunkcum[c][key] = run;
        run += x;
    }
    g_keytot[key] = run;
}

// ---------------- P2b: scan key totals in smem (1 block x 256 thr) ----------------
__global__ void k_scan2() {
    __shared__ int sh[NKEY];
    __shared__ int ssum[256];
    const int tid = threadIdx.x;
    for (int j = tid; j < NKEY; j += 256) sh[j] = g_keytot[j];   // coalesced
    __syncthreads();
    int lsum = 0, lpre[16];
#pragma unroll
    for (int q = 0; q < 16; q++) { lpre[q] = lsum; lsum += sh[tid * 16 + q]; }
    ssum[tid] = lsum;
    __syncthreads();
    for (int ofs = 1; ofs < 256; ofs <<= 1) {        // Hillis-Steele inclusive
        int v = (tid >= ofs) ? ssum[tid - ofs] : 0;
        __syncthreads();
        ssum[tid] += v;
        __syncthreads();
    }
    const int base = ssum[tid] - lsum;               // exclusive prefix
#pragma unroll
    for (int q = 0; q < 16; q++) g_binoff[tid * 16 + q] = base + lpre[q];
    if (tid == 255) g_binoff[NKEY] = base + lsum;
}

// ---------------- P3: stable scatter + point preprocessing ----------------
__global__ void k_scatter(const float* __restrict__ S,
                          const float* __restrict__ alpha,
                          int n, int nchunks) {
    __shared__ int   keys[256];
    __shared__ float st[256], sv[256];
    const int tid = threadIdx.x;
    const int c   = blockIdx.x;

    if (c == 0 && tid < NDIM) {          // publish per-dim v sums
        ull acc = 0ULL;
        for (int cc = 0; cc < nchunks; cc++) acc += g_chunkvsum[cc][tid];
        g_sumv[tid] = (float)((long long)acc) * VSCALE_INV;
    }

    int i = c * 256 + tid;
    int key = -1;
    if (i < n) {
        float t = S[i * 3 + 0];
        st[tid] = t;
        sv[tid] = S[i * 3 + 1];
        int d = (int)S[i * 3 + 2];
        int tb = (int)(t * (float)TBINS);
        tb = max(0, min(TBINS - 1, tb));
        key = d * TBINS + tb;
    }
    keys[tid] = key;
    __syncthreads();
    if (key >= 0) {
        int rank = 0;
        for (int j = 0; j < tid; j++) rank += (keys[j] == key);
        int pos = g_binoff[key] + g_chunkcum[c][key] + rank;

        float t = st[tid];
        float tm = (t > 0.0f) ? t : 1.0e9f;     // masked -> exp underflows to 0
        float negC = -__ldg(alpha) * LOG2E;
        float B = -2.0f * negC * tm;            // arg = A + B*r + C = negC*(r-t)^2
        float Cc = negC * tm * tm;
        ulonglong2 bc;
        bc.x = pack2(B, B);
        bc.y = pack2(Cc, Cc);
        g_bc[pos] = bc;
        g_vv[pos] = pack2(sv[tid], sv[tid]);
    }
}

// ---------------- Ks kernel: full 67M pairs, light body ----------------
// grid = (R/(TPB*RPT)=4, NDIM, NSPLIT=8) = 2048 CTAs x 128 thr
__global__ void __launch_bounds__(TPB) k_main_s(const float* __restrict__ ref,
                                                const float* __restrict__ alpha,
                                                int R) {
    const int d   = blockIdx.y;
    const int z   = blockIdx.z;
    const int lo0 = g_binoff[d * TBINS];
    const int len = g_binoff[(d + 1) * TBINS] - lo0;
    const int lo  = lo0 + (len * z) / NSPLIT;
    const int hi  = lo0 + (len * (z + 1)) / NSPLIT;
    const int tid = threadIdx.x;
    const int r0  = blockIdx.x * (TPB * RPT) + tid;

    const float negC = -__ldg(alpha) * LOG2E;
    const float f0 = __ldg(ref + r0),           f1 = __ldg(ref + r0 + TPB);
    const float f2 = __ldg(ref + r0 + 2 * TPB), f3 = __ldg(ref + r0 + 3 * TPB);
    const ull rr01 = pack2(f0, f1);
    const ull rr23 = pack2(f2, f3);
    const ull A01  = pack2(negC * f0 * f0, negC * f1 * f1);
    const ull A23  = pack2(negC * f2 * f2, negC * f3 * f3);

    ull ws01 = 0, wsv01 = 0, ws23 = 0, wsv23 = 0;

#pragma unroll 4
    for (int i = lo; i < hi; i++) {
        ulonglong2 bc = __ldg(&g_bc[i]);
        ull vp = __ldg(&g_vv[i]);

        ull pc01 = add2(bc.y, A01);
        ull pc23 = add2(bc.y, A23);
        ull g01  = fma2(bc.x, rr01, pc01);    // negC*(r-t)^2 in log2 domain
        ull g23  = fma2(bc.x, rr23, pc23);

        float a0, a1, a2, a3;
        unpack2(g01, a0, a1);
        unpack2(g23, a2, a3);
        ull e01 = pack2(ex2f(a0), ex2f(a1));
        ull e23 = pack2(ex2f(a2), ex2f(a3));

        ws01  = add2(ws01, e01);
        wsv01 = fma2(e01, vp, wsv01);
        ws23  = add2(ws23, e23);
        wsv23 = fma2(e23, vp, wsv23);
    }

    float x0, x1;
    const int base = d * R + r0;
    unpack2(ws01,  x0, x1); g_Sws [z][base] = x0; g_Sws [z][base + TPB] = x1;
    unpack2(ws23,  x0, x1); g_Sws [z][base + 2 * TPB] = x0; g_Sws [z][base + 3 * TPB] = x1;
    unpack2(wsv01, x0, x1); g_Swsv[z][base] = x0; g_Swsv[z][base + TPB] = x1;
    unpack2(wsv23, x0, x1); g_Swsv[z][base + 2 * TPB] = x0; g_Swsv[z][base + 3 * TPB] = x1;
}

// ---------------- Kc kernel: windowed pairs, e^10 = ex2(10*arg) ----------------
// grid = (R/128=16, NDIM, NSPLITC=2), 64 threads; block covers 128 contiguous r's
__global__ void __launch_bounds__(64) k_main_c(const float* __restrict__ ref,
                                               const float* __restrict__ alpha,
                                               int R) {
    const int d   = blockIdx.y;
    const int z   = blockIdx.z;
    const int tid = threadIdx.x;
    const int rb  = blockIdx.x * 128;

    const float negC10 = -10.0f * __ldg(alpha) * LOG2E;
    const float f0 = __ldg(ref + rb + tid);
    const float f1 = __ldg(ref + rb + tid + 64);
    const ull rr01 = pack2(10.0f * f0, 10.0f * f1);          // 10*r
    const ull A01  = pack2(negC10 * f0 * f0, negC10 * f1 * f1);
    const ull TEN2 = pack2(10.0f, 10.0f);

    // window: bins intersecting [rlo-DW, rhi+DW]
    const float rlo = __ldg(ref + rb);
    const float rhi = __ldg(ref + rb + 127);
    int b0 = (int)floorf((rlo - DW) * (float)TBINS);
    int b1 = (int)floorf((rhi + DW) * (float)TBINS) + 1;
    b0 = max(0, b0); b1 = min(TBINS, b1);
    const int p0  = g_binoff[d * TBINS + b0];
    const int p1  = g_binoff[d * TBINS + b1];
    const int len = p1 - p0;
    const int lo  = p0 + (len * z) / NSPLITC;
    const int hi  = p0 + (len * (z + 1)) / NSPLITC;

    ull wc01 = 0, wcv01 = 0;

#pragma unroll 4
    for (int i = lo; i < hi; i++) {
        ulonglong2 bc = __ldg(&g_bc[i]);      // {B,B},{C,C}
        ull vp = __ldg(&g_vv[i]);

        ull pc  = fma2(bc.y, TEN2, A01);      // 10C + 10A
        ull g01 = fma2(bc.x, rr01, pc);       // B*(10r) + 10C + 10A = 10*arg

        float a0, a1;
        unpack2(g01, a0, a1);
        ull e01 = pack2(ex2f(a0), ex2f(a1));  // e^10 directly

        wc01  = add2(wc01, e01);
        wcv01 = fma2(e01, vp, wcv01);
    }

    float x0, x1;
    const int base = d * R + rb + tid;
    unpack2(wc01,  x0, x1); g_Swc [z][base] = x0; g_Swc [z][base + 64] = x1;
    unpack2(wcv01, x0, x1); g_Swcv[z][base] = x0; g_Swcv[z][base + 64] = x1;
}

// ---------------- finalize: 512 blocks x 256 thr, 4 r's per block ----------------
__global__ void __launch_bounds__(256) k_finalize(const float* __restrict__ rho,
                                                  float* __restrict__ out,
                                                  int R, float Rinv) {
    __shared__ float s_lam[4][NDIM + 1];
    __shared__ float s_ksv[4][NDIM + 1];
    __shared__ float s_coa[4][NDIM + 1];
    __shared__ float s_den[4];

    const int tid = threadIdx.x;
    const int r0  = blockIdx.x * 4;

    {
        const int d   = tid >> 2;
        const int rl  = tid & 3;
        const int idx = d * R + r0 + rl;
        const int cnt = g_binoff[(d + 1) * TBINS] - g_binoff[d * TBINS];
        const float ec = EPS * (float)(cnt + 1);
        const float ev = EPS * g_sumv[d];
        float lam_s = ec, ksv = ev;
#pragma unroll
        for (int zz = 0; zz < NSPLIT; zz++) {
            lam_s += g_Sws [zz][idx];
            ksv   += g_Swsv[zz][idx];
        }
        float lam_c = g_Swc [0][idx] + g_Swc [1][idx] + ec;
        float kcv   = g_Swcv[0][idx] + g_Swcv[1][idx] + ev;
        s_lam[rl][d] = lam_s;
        s_ksv[rl][d] = ksv;
        s_coa[rl][d] = __fdividef(kcv, lam_c);
    }
    __syncthreads();

    {
        const int wid  = tid >> 5;
        const int lane = tid & 31;
        if (wid < 4) {
            float p = s_lam[wid][lane] + s_lam[wid][lane + 32];
            p += __shfl_xor_sync(0xffffffffu, p, 16);
            p += __shfl_xor_sync(0xffffffffu, p, 8);
            p += __shfl_xor_sync(0xffffffffu, p, 4);
            p += __shfl_xor_sync(0xffffffffu, p, 2);
            p += __shfl_xor_sync(0xffffffffu, p, 1);
            if (lane == 0) s_den[wid] = p;
        }
    }
    __syncthreads();

    const int d  = tid & 63;
    const int rl = tid >> 6;
    float acc = 0.0f;
#pragma unroll
    for (int k = 0; k < NDIM; k++)
        acc = fmaf(s_ksv[rl][k], __ldg(&rho[k * NDIM + d]), acc);
    const float cr = __fdividef(acc, s_den[rl]);

    const int r = r0 + rl;
    float* o = out + (long long)r * (3 * NDIM);
    o[d]            = s_lam[rl][d] * Rinv;   // lam
    o[NDIM + d]     = cr;                    // cross
    o[2 * NDIM + d] = s_coa[rl][d] - cr;     // transient
}

// ---------------- launch ----------------
extern "C" void kernel_launch(void* const* d_in, const int* in_sizes, int n_in,
                              void* d_out, int out_size) {
    const float* S     = (const float*)d_in[0];
    const float* ref   = (const float*)d_in[1];
    const float* alpha = (const float*)d_in[2];
    const float* rho   = (const float*)d_in[3];
    const int n = in_sizes[0] / 3;
    const int R = in_sizes[1];
    int nchunks = (n + 255) / 256;
    if (nchunks > MAXCHUNKS) nchunks = MAXCHUNKS;

    k_hist<<<nchunks, 256>>>(S, n);
    k_scan1<<<NKEY / 256, 256>>>(nchunks);
    k_scan2<<<1, 256>>>();
    k_scatter<<<nchunks, 256>>>(S, alpha, n, nchunks);

    dim3 gs(R / (TPB * RPT), NDIM, NSPLIT);
    k_main_s<<<gs, TPB>>>(ref, alpha, R);

    dim3 gc(R / 128, NDIM, NSPLITC);
    k_main_c<<<gc, 64>>>(ref, alpha, R);

    k_finalize<<<R / 4, 256>>>(rho, (float*)d_out, R, 1.0f / (float)R);
}

// round 10
// speedup vs baseline: 8.6496x; 1.1273x over previous
#include <cuda_runtime.h>

#define EPS 1e-7f
#define NDIM 64
#define TBINS 32
#define NKEY (NDIM * TBINS)          // 2048 sort keys
#define MAXN 32768
#define MAXR 2048
#define MAXCHUNKS 128
#define NSPLIT 4  // point-splits for main kernel
#define DWS 0.42f // Ks window half-width: tail rel err ~1.4e-5
#define DWC 0.19f // Kc window half-width: exp(-500*0.19^2)=1.5e-8
#define LOG2E 1.4426950408889634f
#define VSCALE 8388608.0f
#define VSCALE_INV 1.1920928955078125e-7f

typedef unsigned long long ull;

// ---------------- device scratch ----------------
__device__ ulonglong2 g_bc[MAXN];               // {B,B},{C,C} per point, (d,tbin)-sorted
__device__ ull    g_vv[MAXN];                   // {v,v}
__device__ int    g_binoff[NKEY + 1];           // global offset per key
__device__ int    g_keytot[NKEY];               // total count per key
__device__ int    g_chunkhist[MAXCHUNKS][NKEY]; // [chunk][key] (coalesced)
__device__ int    g_chunkcum [MAXCHUNKS][NKEY]; // exclusive chunk prefix per key
__device__ ull    g_chunkvsum[MAXCHUNKS][NDIM];
__device__ float  g_sumv[NDIM];
__device__ float  g_Sws [NSPLIT][NDIM * MAXR];  // sum e
__device__ float  g_Swsv[NSPLIT][NDIM * MAXR];  // sum e*v
__device__ float  g_Swc [NSPLIT][NDIM * MAXR];  // sum e^10
__device__ float  g_Swcv[NSPLIT][NDIM * MAXR];  // sum e^10*v

// ---------------- f32x2 packed helpers (sm_100a) ----------------
__device__ __forceinline__ ull pack2(float lo, float hi) {
    ull r; asm("mov.b64 %0, {%1, %2};" : "=l"(r) : "f"(lo), "f"(hi)); return r;
}
__device__ __forceinline__ void unpack2(ull p, float& lo, float& hi) {
    asm("mov.b64 {%0, %1}, %2;" : "=f"(lo), "=f"(hi) : "l"(p));
}
__device__ __forceinline__ ull add2(ull a, ull b) {
    ull r; asm("add.rn.f32x2 %0, %1, %2;" : "=l"(r) : "l"(a), "l"(b)); return r;
}
__device__ __forceinline__ ull mul2(ull a, ull b) {
    ull r; asm("mul.rn.f32x2 %0, %1, %2;" : "=l"(r) : "l"(a), "l"(b)); return r;
}
__device__ __forceinline__ ull fma2(ull a, ull b, ull c) {
    ull r; asm("fma.rn.f32x2 %0, %1, %2, %3;" : "=l"(r) : "l"(a), "l"(b), "l"(c)); return r;
}
__device__ __forceinline__ float ex2f(float x) {
    float y; asm("ex2.approx.f32 %0, %1;" : "=f"(y) : "f"(x)); return y;
}

// ---------------- P1: per-chunk 2048-key histogram + per-dim v sums ----------------
__global__ void k_hist(const float* __restrict__ S, int n) {
    __shared__ int h[NKEY];
    __shared__ ull vs[NDIM];
    const int tid = threadIdx.x;
    for (int j = tid; j < NKEY; j += 256) h[j] = 0;
    if (tid < NDIM) vs[tid] = 0ULL;
    __syncthreads();
    int i = blockIdx.x * 256 + tid;
    if (i < n) {
        float t = S[i * 3 + 0];
        float v = S[i * 3 + 1];
        int d = (int)S[i * 3 + 2];
        int tb = (int)(t * (float)TBINS);
        tb = max(0, min(TBINS - 1, tb));
        atomicAdd(&h[d * TBINS + tb], 1);
        atomicAdd(&vs[d], (ull)(long long)llrintf(v * VSCALE));
    }
    __syncthreads();
    for (int j = tid; j < NKEY; j += 256) g_chunkhist[blockIdx.x][j] = h[j];  // coalesced
    if (tid < NDIM) g_chunkvsum[blockIdx.x][tid] = vs[tid];
}

// ---------------- P2a: per-key chunk scan (8 blocks x 256 thr, 1 thread/key) ----------
__global__ void k_scan1(int nchunks) {
    const int key = blockIdx.x * 256 + threadIdx.x;   // 2048 threads
    int run = 0;
    for (int c = 0; c < nchunks; c++) {               // coalesced across threads
        int x = g_chunkhist[c][key];
        g_chunkcum[c][key] = run;
        run += x;
    }
    g_keytot[key] = run;
}

// ---------------- P2b: scan key totals + parallel per-dim v-sum reduce ----------------
__global__ void k_scan2(int nchunks) {
    __shared__ int sh[NKEY];
    __shared__ int ssum[256];
    __shared__ ull vred[256];
    const int tid = threadIdx.x;
    for (int j = tid; j < NKEY; j += 256) sh[j] = g_keytot[j];   // coalesced
    // g_sumv: thread (d = tid>>2, q = tid&3) sums chunks q, q+4, ...
    {
        const int d = tid >> 2, q = tid & 3;
        ull acc = 0ULL;
        for (int c = q; c < nchunks; c += 4) acc += g_chunkvsum[c][d];
        vred[tid] = acc;
    }
    __syncthreads();
    if ((tid & 3) == 0) {
        ull a = vred[tid] + vred[tid + 1] + vred[tid + 2] + vred[tid + 3];
        g_sumv[tid >> 2] = (float)((long long)a) * VSCALE_INV;
    }
    int lsum = 0, lpre[8];
#pragma unroll
    for (int q = 0; q < 8; q++) { lpre[q] = lsum; lsum += sh[tid * 8 + q]; }
    ssum[tid] = lsum;
    __syncthreads();
    for (int ofs = 1; ofs < 256; ofs <<= 1) {        // Hillis-Steele inclusive
        int v = (tid >= ofs) ? ssum[tid - ofs] : 0;
        __syncthreads();
        ssum[tid] += v;
        __syncthreads();
    }
    const int base = ssum[tid] - lsum;               // exclusive prefix
#pragma unroll
    for (int q = 0; q < 8; q++) g_binoff[tid * 8 + q] = base + lpre[q];
    if (tid == 255) g_binoff[NKEY] = base + lsum;
}

// ---------------- P3: stable scatter via match_any + sequential warp offsets --------
__global__ void k_scatter(const float* __restrict__ S,
                          const float* __restrict__ alpha,
                          int n) {
    __shared__ int kc[NKEY];
    const int tid  = threadIdx.x;
    const int c    = blockIdx.x;
    const int lane = tid & 31;
    const int warp = tid >> 5;

    for (int j = tid; j < NKEY; j += 256) kc[j] = 0;

    int i = c * 256 + tid;
    int key = -1;
    float t = 0.f, v = 0.f;
    if (i < n) {
        t = S[i * 3 + 0];
        v = S[i * 3 + 1];
        int d = (int)S[i * 3 + 2];
        int tb = (int)(t * (float)TBINS);
        tb = max(0, min(TBINS - 1, tb));
        key = d * TBINS + tb;
    }
    __syncthreads();

    // intra-warp stable rank among equal keys
    unsigned m  = __match_any_sync(0xffffffffu, key);
    int rw      = __popc(m & ((1u << lane) - 1));
    int ldr     = __ffs(m) - 1;

    // cross-warp: warps take turns bumping per-key counters (deterministic)
    int grpbase = 0;
    for (int w = 0; w < 8; w++) {
        if (warp == w && key >= 0) {
            int gb = 0;
            if (lane == ldr) { gb = kc[key]; kc[key] = gb + __popc(m); }
            grpbase = __shfl_sync(m, gb, ldr);
        }
        __syncthreads();
    }

    if (key >= 0) {
        int pos = g_binoff[key] + g_chunkcum[c][key] + grpbase + rw;
        float tm = (t > 0.0f) ? t : 1.0e9f;     // masked -> exp underflows to 0
        float negC = -__ldg(alpha) * LOG2E;
        float B = -2.0f * negC * tm;            // arg = A + B*r + C = negC*(r-t)^2
        float Cc = negC * tm * tm;
        ulonglong2 bc;
        bc.x = pack2(B, B);
        bc.y = pack2(Cc, Cc);
        g_bc[pos] = bc;
        g_vv[pos] = pack2(v, v);
    }
}

// ---------------- merged main: windowed Ks (±0.42) + nested windowed Kc (±0.19) -----
// grid = (R/128=16, NDIM, NSPLIT=4) = 4096 CTAs x 64 thr; block covers 128 contiguous r's
__global__ void __launch_bounds__(64) k_main(const float* __restrict__ ref,
                                             const float* __restrict__ alpha,
                                             int R) {
    const int d   = blockIdx.y;
    const int z   = blockIdx.z;
    const int tid = threadIdx.x;
    const int rb  = blockIdx.x * 128;

    const float negC = -__ldg(alpha) * LOG2E;
    const float f0 = __ldg(ref + rb + tid);
    const float f1 = __ldg(ref + rb + tid + 64);
    const ull rr  = pack2(f0, f1);
    const ull A   = pack2(negC * f0 * f0, negC * f1 * f1);
    const ull TEN2 = pack2(10.0f, 10.0f);

    const float rlo = __ldg(ref + rb);
    const float rhi = __ldg(ref + rb + 127);

    // Ks window bins
    int sb0 = max(0, (int)floorf((rlo - DWS) * (float)TBINS));
    int sb1 = min(TBINS, (int)floorf((rhi + DWS) * (float)TBINS) + 1);
    const int s0 = g_binoff[d * TBINS + sb0];
    const int s1 = g_binoff[d * TBINS + sb1];
    // Kc window bins (nested)
    int cb0 = max(0, (int)floorf((rlo - DWC) * (float)TBINS));
    int cb1 = min(TBINS, (int)floorf((rhi + DWC) * (float)TBINS) + 1);
    const int c0 = g_binoff[d * TBINS + cb0];
    const int c1 = g_binoff[d * TBINS + cb1];

    const int len = s1 - s0;
    const int lo  = s0 + (len * z) / NSPLIT;
    const int hi  = s0 + (len * (z + 1)) / NSPLIT;

    ull ws = 0, wsv = 0, wc = 0, wcv = 0;

#pragma unroll 2
    for (int i = lo; i < hi; i++) {
        ulonglong2 bc = __ldg(&g_bc[i]);      // {B,B},{C,C}
        ull vp = __ldg(&g_vv[i]);             // {v,v}

        ull g = fma2(bc.x, rr, add2(bc.y, A));   // negC*(r-t)^2 (log2 domain)
        float a0, a1;
        unpack2(g, a0, a1);
        ull e = pack2(ex2f(a0), ex2f(a1));
        ws  = add2(ws, e);
        wsv = fma2(e, vp, wsv);

        if (i >= c0 && i < c1) {              // uniform branch per block
            ull g10 = mul2(g, TEN2);
            float b0f, b1f;
            unpack2(g10, b0f, b1f);
            ull e10 = pack2(ex2f(b0f), ex2f(b1f));
            wc  = add2(wc, e10);
            wcv = fma2(e10, vp, wcv);
        }
    }

    float x0, x1;
    const int base = d * R + rb + tid;
    unpack2(ws,  x0, x1); g_Sws [z][base] = x0; g_Sws [z][base + 64] = x1;
    unpack2(wsv, x0, x1); g_Swsv[z][base] = x0; g_Swsv[z][base + 64] = x1;
    unpack2(wc,  x0, x1); g_Swc [z][base] = x0; g_Swc [z][base + 64] = x1;
    unpack2(wcv, x0, x1); g_Swcv[z][base] = x0; g_Swcv[z][base + 64] = x1;
}

// ---------------- finalize: 512 blocks x 256 thr, 4 r's per block ----------------
__global__ void __launch_bounds__(256) k_finalize(const float* __restrict__ rho,
                                                  float* __restrict__ out,
                                                  int R, float Rinv) {
    __shared__ float s_lam[4][NDIM + 1];
    __shared__ float s_ksv[4][NDIM + 1];
    __shared__ float s_coa[4][NDIM + 1];
    __shared__ float s_den[4];

    const int tid = threadIdx.x;
    const int r0  = blockIdx.x * 4;

    {
        const int d   = tid >> 2;
        const int rl  = tid & 3;
        const int idx = d * R + r0 + rl;
        const int cnt = g_binoff[(d + 1) * TBINS] - g_binoff[d * TBINS];
        const float ec = EPS * (float)(cnt + 1);
        const float ev = EPS * g_sumv[d];
        float lam_s = ec, ksv = ev, lam_c = ec, kcv = ev;
#pragma unroll
        for (int zz = 0; zz < NSPLIT; zz++) {
            lam_s += g_Sws [zz][idx];
            ksv   += g_Swsv[zz][idx];
            lam_c += g_Swc [zz][idx];
            kcv   += g_Swcv[zz][idx];
        }
        s_lam[rl][d] = lam_s;
        s_ksv[rl][d] = ksv;
        s_coa[rl][d] = __fdividef(kcv, lam_c);
    }
    __syncthreads();

    {
        const int wid  = tid >> 5;
        const int lane = tid & 31;
        if (wid < 4) {
            float p = s_lam[wid][lane] + s_lam[wid][lane + 32];
            p += __shfl_xor_sync(0xffffffffu, p, 16);
            p += __shfl_xor_sync(0xffffffffu, p, 8);
            p += __shfl_xor_sync(0xffffffffu, p, 4);
            p += __shfl_xor_sync(0xffffffffu, p, 2);
            p += __shfl_xor_sync(0xffffffffu, p, 1);
            if (lane == 0) s_den[wid] = p;
        }
    }
    __syncthreads();

    const int d  = tid & 63;
    const int rl = tid >> 6;
    float acc = 0.0f;
#pragma unroll
    for (int k = 0; k < NDIM; k++)
        acc = fmaf(s_ksv[rl][k], __ldg(&rho[k * NDIM + d]), acc);
    const float cr = __fdividef(acc, s_den[rl]);

    const int r = r0 + rl;
    float* o = out + (long long)r * (3 * NDIM);
    o[d]            = s_lam[rl][d] * Rinv;   // lam
    o[NDIM + d]     = cr;                    // cross
    o[2 * NDIM + d] = s_coa[rl][d] - cr;     // transient
}

// ---------------- launch ----------------
extern "C" void kernel_launch(void* const* d_in, const int* in_sizes, int n_in,
                              void* d_out, int out_size) {
    const float* S     = (const float*)d_in[0];
    const float* ref   = (const float*)d_in[1];
    const float* alpha = (const float*)d_in[2];
    const float* rho   = (const float*)d_in[3];
    const int n = in_sizes[0] / 3;
    const int R = in_sizes[1];
    int nchunks = (n + 255) / 256;
    if (nchunks > MAXCHUNKS) nchunks = MAXCHUNKS;

    k_hist<<<nchunks, 256>>>(S, n);
    k_scan1<<<NKEY / 256, 256>>>(nchunks);
    k_scan2<<<1, 256>>>(nchunks);
    k_scatter<<<nchunks, 256>>>(S, alpha, n);

    dim3 gm(R / 128, NDIM, NSPLIT);
    k_main<<<gm, 64>>>(ref, alpha, R);

    k_finalize<<<R / 4, 256>>>(rho, (float*)d_out, R, 1.0f / (float)R);
}